// round 5
// baseline (speedup 1.0000x reference)
#include <cuda_runtime.h>
#include <cstdint>

#define B_ 8
#define V_ 49
#define H_ 128
#define W_ 128
#define F_ 64

#define DEPTH 4
#define CHUNK_H 16                              // h-rows per item
#define ITEM_BYTES (CHUNK_H * W_ * 4)           // 8192
#define GROUPS_PER_BV (H_ / CHUNK_H)            // 8
#define N_ITEMS (B_ * GROUPS_PER_BV * V_)       // 3136, ordered i = (b*8+o)*49 + v
#define GRID 148
#define NTHREADS 256
#define MSTRIDE 66                              // padded mask row (conflict-free)

__device__ __forceinline__ uint32_t smem_u32(const void* p) {
    return (uint32_t)__cvta_generic_to_shared(p);
}
__device__ __forceinline__ void mbar_init(uint32_t bar, uint32_t cnt) {
    asm volatile("mbarrier.init.shared.b64 [%0], %1;" :: "r"(bar), "r"(cnt) : "memory");
}
__device__ __forceinline__ void mbar_arrive(uint32_t bar) {
    asm volatile("mbarrier.arrive.shared.b64 _, [%0];" :: "r"(bar) : "memory");
}
__device__ __forceinline__ void mbar_expect_tx(uint32_t bar, uint32_t bytes) {
    asm volatile("mbarrier.arrive.expect_tx.shared.b64 _, [%0], %1;"
                 :: "r"(bar), "r"(bytes) : "memory");
}
__device__ __forceinline__ void mbar_wait(uint32_t bar, uint32_t parity) {
    asm volatile(
        "{\n\t.reg .pred P;\n\t"
        "WL_%=:\n\t"
        "mbarrier.try_wait.parity.acquire.cta.shared::cta.b64 P, [%0], %1, 0x989680;\n\t"
        "@P bra DONE_%=;\n\t"
        "bra WL_%=;\n\t"
        "DONE_%=:\n\t}"
        :: "r"(bar), "r"(parity) : "memory");
}
__device__ __forceinline__ void bulk_g2s(uint32_t dst, const void* src,
                                         uint32_t bytes, uint32_t bar) {
    asm volatile(
        "cp.async.bulk.shared::cluster.global.mbarrier::complete_tx::bytes "
        "[%0], [%1], %2, [%3];"
        :: "r"(dst), "l"(src), "r"(bytes), "r"(bar) : "memory");
}

__global__ void __launch_bounds__(NTHREADS, 1)
depth_cue_kernel(const float* __restrict__ lfi,
                 const float* __restrict__ h_mask,
                 float2* __restrict__ out2) {
    __shared__ __align__(128) float buf[DEPTH][CHUNK_H * W_];   // 4 x 8KB
    __shared__ __align__(16)  float m_s[CHUNK_H * MSTRIDE];     // ~4.1KB
    __shared__ __align__(8)   unsigned long long full_bar[DEPTH];
    __shared__ __align__(8)   unsigned long long empty_bar[DEPTH];

    const int tid  = threadIdx.x;
    const int wid  = tid >> 5;
    const int lane = tid & 31;

    const int start = (blockIdx.x * N_ITEMS) / GRID;
    const int end   = ((blockIdx.x + 1) * N_ITEMS) / GRID;

    const uint32_t full0  = smem_u32(full_bar);
    const uint32_t empty0 = smem_u32(empty_bar);

    if (tid == 0) {
        #pragma unroll
        for (int s = 0; s < DEPTH; s++) {
            mbar_init(full0  + 8u * s, 1);   // 1 expect_tx arrive
            mbar_init(empty0 + 8u * s, 8);   // 8 warp arrivals
        }
    }
    __syncthreads();

    // Prologue: fill the ring (first use of each slot needs no empty-wait)
    if (tid == 0) {
        #pragma unroll
        for (int k = 0; k < DEPTH; k++) {
            int i = start + k;               // end-start >= 21 > DEPTH always
            int g = i / V_, v = i - g * V_;
            int b = g >> 3, o = g & 7;
            const float* src = lfi + ((size_t)((b * V_ + v) * H_ + o * CHUNK_H)) * W_;
            mbar_expect_tx(full0 + 8u * k, ITEM_BYTES);
            bulk_g2s(smem_u32(buf[k]), src, ITEM_BYTES, full0 + 8u * k);
        }
    }

    int cur_g = -1;
    for (int i = start; i < end; i++) {
        const int rel  = i - start;
        const int slot = rel & (DEPTH - 1);
        const int use  = rel >> 2;           // log2(DEPTH)
        const int g = i / V_, v = i - g * V_;
        const int b = g >> 3, o = g & 7;

        // Mask group change (<=3 per block): m_s[h][f] = W * h_mask[b,f,o*16+h]
        if (g != cur_g) {
            __syncthreads();                 // old m_s fully consumed
            for (int e = tid; e < CHUNK_H * F_; e += NTHREADS) {
                int f = e >> 4, h = e & 15;
                m_s[h * MSTRIDE + f] =
                    (float)W_ * h_mask[((b << 6) + f) * H_ + (o * CHUNK_H + h)];
            }
            __syncthreads();
            cur_g = g;
        }

        // Wait for this slot's TMA data
        mbar_wait(full0 + 8u * slot, use & 1);

        // Warp wid owns rows 2*wid, 2*wid+1 of the 16-row chunk
        const float4* bp = (const float4*)buf[slot];
        float4 x = bp[(2 * wid)     * 32 + lane];
        float4 y = bp[(2 * wid + 1) * 32 + lane];
        float s0 = (x.x + x.y) + (x.z + x.w);
        float s1 = (y.x + y.y) + (y.z + y.w);
        #pragma unroll
        for (int off = 16; off > 0; off >>= 1) {
            s0 += __shfl_xor_sync(0xffffffffu, s0, off);
            s1 += __shfl_xor_sync(0xffffffffu, s1, off);
        }

        float2 m0 = *(const float2*)&m_s[(2 * wid)     * MSTRIDE + 2 * lane];
        float2 m1 = *(const float2*)&m_s[(2 * wid + 1) * MSTRIDE + 2 * lane];

        const size_t row0 = (size_t)((b * V_ + v) * H_ + o * CHUNK_H);
        out2[(row0 + 2 * wid)     * 32 + lane] = make_float2(s0 + m0.x, s0 + m0.y);
        out2[(row0 + 2 * wid + 1) * 32 + lane] = make_float2(s1 + m1.x, s1 + m1.y);

        // Release the slot (one arrive per warp)
        if (lane == 0) mbar_arrive(empty0 + 8u * slot);

        // Producer: refill this slot with item i+DEPTH once all warps released it
        if (tid == 0 && i + DEPTH < end) {
            mbar_wait(empty0 + 8u * slot, use & 1);
            const int j = i + DEPTH;
            const int gj = j / V_, vj = j - gj * V_;
            const int bj = gj >> 3, oj = gj & 7;
            const float* src =
                lfi + ((size_t)((bj * V_ + vj) * H_ + oj * CHUNK_H)) * W_;
            mbar_expect_tx(full0 + 8u * slot, ITEM_BYTES);
            bulk_g2s(smem_u32(buf[slot]), src, ITEM_BYTES, full0 + 8u * slot);
        }
    }
}

extern "C" void kernel_launch(void* const* d_in, const int* in_sizes, int n_in,
                              void* d_out, int out_size) {
    // Identify inputs by element count (robust to ordering):
    //   lfi    : B*V*H*W = 6,422,528
    //   f_maps : B*H*W*F = 8,388,608 (dead input — never touched)
    //   h_mask : B*F*H   = 65,536
    const float* lfi = nullptr;
    const float* h_mask = nullptr;
    for (int i = 0; i < n_in; i++) {
        if (in_sizes[i] == B_ * V_ * H_ * W_) lfi = (const float*)d_in[i];
        else if (in_sizes[i] == B_ * F_ * H_) h_mask = (const float*)d_in[i];
    }
    depth_cue_kernel<<<GRID, NTHREADS>>>(lfi, h_mask, (float2*)d_out);
}

// round 6
// speedup vs baseline: 1.2461x; 1.2461x over previous
#include <cuda_runtime.h>
#include <cstdint>

#define B_ 8
#define V_ 49
#define H_ 128
#define W_ 128
#define F_ 64

#define DEPTH 4
#define ROWS_PER_ITEM 64                         // half an h-plane
#define ITEM_BYTES (ROWS_PER_ITEM * W_ * 4)      // 32768
#define ITEMS_PER_B (V_ * 2)                     // 98
#define N_ITEMS (B_ * ITEMS_PER_B)               // 784
#define GRID 148
#define NCONS 256                                // 8 consumer warps
#define NTHREADS 288                             // + 1 producer warp
#define MSTRIDE 66                               // padded mask row stride (floats)

#define BUF_OFF   0
#define BUF_BYTES (DEPTH * ITEM_BYTES)           // 131072
#define MASK_OFF  BUF_BYTES                      // 131072
#define MASK_BYTES (H_ * MSTRIDE * 4)            // 33792
#define BAR_OFF   (MASK_OFF + MASK_BYTES)        // 164864
#define SMEM_TOTAL (BAR_OFF + 64)

__device__ __forceinline__ uint32_t smem_u32(const void* p) {
    return (uint32_t)__cvta_generic_to_shared(p);
}
__device__ __forceinline__ void mbar_init(uint32_t bar, uint32_t cnt) {
    asm volatile("mbarrier.init.shared.b64 [%0], %1;" :: "r"(bar), "r"(cnt) : "memory");
}
__device__ __forceinline__ void mbar_arrive(uint32_t bar) {
    asm volatile("mbarrier.arrive.shared.b64 _, [%0];" :: "r"(bar) : "memory");
}
__device__ __forceinline__ void mbar_expect_tx(uint32_t bar, uint32_t bytes) {
    asm volatile("mbarrier.arrive.expect_tx.shared.b64 _, [%0], %1;"
                 :: "r"(bar), "r"(bytes) : "memory");
}
__device__ __forceinline__ void mbar_wait(uint32_t bar, uint32_t parity) {
    asm volatile(
        "{\n\t.reg .pred P;\n\t"
        "WL_%=:\n\t"
        "mbarrier.try_wait.parity.acquire.cta.shared::cta.b64 P, [%0], %1, 0x989680;\n\t"
        "@P bra DONE_%=;\n\t"
        "bra WL_%=;\n\t"
        "DONE_%=:\n\t}"
        :: "r"(bar), "r"(parity) : "memory");
}
__device__ __forceinline__ void bulk_g2s(uint32_t dst, const void* src,
                                         uint32_t bytes, uint32_t bar) {
    asm volatile(
        "cp.async.bulk.shared::cluster.global.mbarrier::complete_tx::bytes "
        "[%0], [%1], %2, [%3];"
        :: "r"(dst), "l"(src), "r"(bytes), "r"(bar) : "memory");
}

// item i: b = i/98, j = i%98, v = j>>1, half = j&1
//   covers lfi rows [(b*49+v)*128 + half*64, +64), 32KB contiguous.
__global__ void __launch_bounds__(NTHREADS, 1)
depth_cue_kernel(const float* __restrict__ lfi,
                 const float* __restrict__ h_mask,
                 float2* __restrict__ out2) {
    extern __shared__ __align__(128) char smem[];
    float*    buf   = (float*)(smem + BUF_OFF);      // [DEPTH][64*128]
    float*    m_s   = (float*)(smem + MASK_OFF);     // [128][MSTRIDE]
    uint32_t  full0  = smem_u32(smem + BAR_OFF);     // DEPTH x 8B
    uint32_t  empty0 = smem_u32(smem + BAR_OFF + DEPTH * 8);

    const int tid  = threadIdx.x;
    const int wid  = tid >> 5;
    const int lane = tid & 31;

    const int start = (blockIdx.x * N_ITEMS) / GRID;
    const int end   = ((blockIdx.x + 1) * N_ITEMS) / GRID;   // >= start+5

    if (tid == 0) {
        #pragma unroll
        for (int s = 0; s < DEPTH; s++) {
            mbar_init(full0  + 8u * s, 1);   // completed by expect_tx's tx-count
            mbar_init(empty0 + 8u * s, 8);   // 8 consumer-warp arrivals
        }
    }
    __syncthreads();   // all 289... 288 threads: barriers visible before use

    if (wid == 8) {
        // ---------------- Producer warp ----------------
        if (lane == 0) {
            const int n = end - start;
            const int npro = n < DEPTH ? n : DEPTH;
            for (int k = 0; k < npro; k++) {
                const int i = start + k;
                const int b = i / ITEMS_PER_B, j = i - b * ITEMS_PER_B;
                const float* src =
                    lfi + ((size_t)((b * V_ + (j >> 1)) * H_ + (j & 1) * ROWS_PER_ITEM)) * W_;
                mbar_expect_tx(full0 + 8u * k, ITEM_BYTES);
                bulk_g2s(smem_u32(buf) + (uint32_t)k * ITEM_BYTES, src,
                         ITEM_BYTES, full0 + 8u * k);
            }
            for (int i = start + DEPTH; i < end; i++) {
                const int rel = i - start;
                const int slot = rel & (DEPTH - 1);
                const int use  = rel >> 2;
                mbar_wait(empty0 + 8u * slot, (use - 1) & 1);
                const int b = i / ITEMS_PER_B, j = i - b * ITEMS_PER_B;
                const float* src =
                    lfi + ((size_t)((b * V_ + (j >> 1)) * H_ + (j & 1) * ROWS_PER_ITEM)) * W_;
                mbar_expect_tx(full0 + 8u * slot, ITEM_BYTES);
                bulk_g2s(smem_u32(buf) + (uint32_t)slot * ITEM_BYTES, src,
                         ITEM_BYTES, full0 + 8u * slot);
            }
        }
        return;
    }

    // ---------------- Consumer warps (0..7) ----------------
    int cur_b = -1;
    for (int i = start; i < end; i++) {
        const int rel  = i - start;
        const int slot = rel & (DEPTH - 1);
        const int use  = rel >> 2;
        const int b = i / ITEMS_PER_B, j = i - b * ITEMS_PER_B;
        const int v = j >> 1, half = j & 1;

        // Per-b mask table: m_s[h][f] = W * h_mask[b,f,h]  (<=2 fills/block)
        if (b != cur_b) {
            asm volatile("bar.sync 1, %0;" :: "r"(NCONS) : "memory");
            for (int e = tid; e < F_ * (H_ / 4); e += NCONS) {
                const int f = e >> 5, h4 = (e & 31) << 2;
                const float4 mv = *(const float4*)&h_mask[(b * F_ + f) * H_ + h4];
                m_s[(h4 + 0) * MSTRIDE + f] = (float)W_ * mv.x;
                m_s[(h4 + 1) * MSTRIDE + f] = (float)W_ * mv.y;
                m_s[(h4 + 2) * MSTRIDE + f] = (float)W_ * mv.z;
                m_s[(h4 + 3) * MSTRIDE + f] = (float)W_ * mv.w;
            }
            asm volatile("bar.sync 1, %0;" :: "r"(NCONS) : "memory");
            cur_b = b;
        }

        mbar_wait(full0 + 8u * slot, use & 1);

        // Warp wid handles 8 rows: r = wid*8 + k
        const float4* bp = (const float4*)(buf + slot * (ROWS_PER_ITEM * W_));
        float s[8];
        #pragma unroll
        for (int k = 0; k < 8; k++) {
            const float4 x = bp[(wid * 8 + k) * 32 + lane];
            s[k] = (x.x + x.y) + (x.z + x.w);
        }
        #pragma unroll
        for (int o = 16; o > 0; o >>= 1) {
            #pragma unroll
            for (int k = 0; k < 8; k++)
                s[k] += __shfl_xor_sync(0xffffffffu, s[k], o);
        }

        const size_t row0 = (size_t)((b * V_ + v) * H_ + half * ROWS_PER_ITEM);
        #pragma unroll
        for (int k = 0; k < 8; k++) {
            const int hl = wid * 8 + k;                  // row in item
            const int hg = half * ROWS_PER_ITEM + hl;    // global h
            const float2 m = *(const float2*)&m_s[hg * MSTRIDE + 2 * lane];
            out2[(row0 + hl) * 32 + lane] = make_float2(s[k] + m.x, s[k] + m.y);
        }

        if (lane == 0) mbar_arrive(empty0 + 8u * slot);
    }
}

extern "C" void kernel_launch(void* const* d_in, const int* in_sizes, int n_in,
                              void* d_out, int out_size) {
    // Identify inputs by element count (robust to ordering):
    //   lfi    : B*V*H*W = 6,422,528
    //   f_maps : B*H*W*F = 8,388,608 (dead input — never touched)
    //   h_mask : B*F*H   = 65,536
    const float* lfi = nullptr;
    const float* h_mask = nullptr;
    for (int i = 0; i < n_in; i++) {
        if (in_sizes[i] == B_ * V_ * H_ * W_) lfi = (const float*)d_in[i];
        else if (in_sizes[i] == B_ * F_ * H_) h_mask = (const float*)d_in[i];
    }

    static bool attr_set = false;
    if (!attr_set) {
        cudaFuncSetAttribute(depth_cue_kernel,
                             cudaFuncAttributeMaxDynamicSharedMemorySize, SMEM_TOTAL);
        attr_set = true;
    }
    depth_cue_kernel<<<GRID, NTHREADS, SMEM_TOTAL>>>(lfi, h_mask, (float2*)d_out);
}

// round 7
// speedup vs baseline: 1.3446x; 1.0791x over previous
#include <cuda_runtime.h>
#include <cstdint>

#define B_ 8
#define V_ 49
#define H_ 128
#define W_ 128
#define F_ 64

// Work item = eighth of an h-plane: 16 consecutive h-rows of one (b,v) = 8KB contiguous.
// Item index u = b*392 + o*49 + v  (o = h-octant 0..7) so consecutive items share the
// same mask group (b,o) for 49 items -> <=2 mask refills per block.
#define ROWS_PER_ITEM 16
#define ITEM_BYTES (ROWS_PER_ITEM * W_ * 4)      // 8192
#define N_ITEMS (B_ * 8 * V_)                    // 3136
#define GRID 296                                  // exactly 2 blocks/SM on 148 SMs
#define NTHREADS 256                              // 8 warps
#define MSTRIDE 66                                // padded mask row stride (floats)

__device__ __forceinline__ void prefetch_l2(const void* p, uint32_t bytes) {
    asm volatile("cp.async.bulk.prefetch.L2.global [%0], %1;"
                 :: "l"(p), "r"(bytes) : "memory");
}

__global__ void __launch_bounds__(NTHREADS, 2)
depth_cue_kernel(const float* __restrict__ lfi,
                 const float* __restrict__ h_mask,
                 float2* __restrict__ out2) {
    __shared__ float m_s[ROWS_PER_ITEM * MSTRIDE];   // mask table for current (b,o)

    const int tid  = threadIdx.x;
    const int wid  = tid >> 5;
    const int lane = tid & 31;

    const int u0 = (int)(((long long)blockIdx.x       * N_ITEMS) / GRID);
    const int u1 = (int)(((long long)(blockIdx.x + 1) * N_ITEMS) / GRID);
    const int n  = u1 - u0;                          // 10 or 11

    // ---- Phase 0: fire L2 prefetches for this block's ENTIRE input range ----
    // Fire-and-forget bulk-async requests: they stream DRAM->L2 without
    // consuming SM-side load tracking. Consumers below then hit L2.
    if (wid == 0 && lane < n) {
        const int u = u0 + lane;
        const int g = u / V_, v = u - g * V_;        // g = b*8 + o
        const int b = g >> 3, o = g & 7;
        const float* src =
            lfi + ((size_t)((b * V_ + v) * H_ + o * ROWS_PER_ITEM)) * W_;
        prefetch_l2(src, ITEM_BYTES);
    }

    // ---- Main loop over items ----
    int cur_g = -1;
    for (int u = u0; u < u1; u++) {
        const int g = u / V_, v = u - g * V_;
        const int b = g >> 3, o = g & 7;

        // Mask group change (<=2 per block): m_s[h][f] = W * h_mask[b,f,o*16+h]
        if (g != cur_g) {
            __syncthreads();                          // old m_s fully consumed
            {
                // 64 f x 16 h = 1024 floats; 256 threads x 1 float4 each
                const int f  = tid >> 2;              // 0..63
                const int hq = (tid & 3) << 2;        // 0,4,8,12
                const float4 mv = *(const float4*)
                    &h_mask[((b << 6) + f) * H_ + o * ROWS_PER_ITEM + hq];
                m_s[(hq + 0) * MSTRIDE + f] = (float)W_ * mv.x;
                m_s[(hq + 1) * MSTRIDE + f] = (float)W_ * mv.y;
                m_s[(hq + 2) * MSTRIDE + f] = (float)W_ * mv.z;
                m_s[(hq + 3) * MSTRIDE + f] = (float)W_ * mv.w;
            }
            __syncthreads();
            cur_g = g;
        }

        // Warp wid owns rows 2*wid and 2*wid+1 of the 16-row item.
        const size_t row_base = (size_t)((b * V_ + v) * H_ + o * ROWS_PER_ITEM);
        const float4* bp = (const float4*)(lfi + row_base * W_);
        const int r0 = wid * 2;

        // Streaming loads (evict-first: read-once data, keep L2 for prefetches)
        const float4 x = __ldcs(&bp[(r0 + 0) * 32 + lane]);
        const float4 y = __ldcs(&bp[(r0 + 1) * 32 + lane]);
        float s0 = (x.x + x.y) + (x.z + x.w);
        float s1 = (y.x + y.y) + (y.z + y.w);
        #pragma unroll
        for (int off = 16; off > 0; off >>= 1) {
            s0 += __shfl_xor_sync(0xffffffffu, s0, off);
            s1 += __shfl_xor_sync(0xffffffffu, s1, off);
        }

        const float2 m0 = *(const float2*)&m_s[(r0 + 0) * MSTRIDE + 2 * lane];
        const float2 m1 = *(const float2*)&m_s[(r0 + 1) * MSTRIDE + 2 * lane];

        // Streaming stores (write-once data)
        __stcs(&out2[(row_base + r0 + 0) * 32 + lane],
               make_float2(s0 + m0.x, s0 + m0.y));
        __stcs(&out2[(row_base + r0 + 1) * 32 + lane],
               make_float2(s1 + m1.x, s1 + m1.y));
    }
}

extern "C" void kernel_launch(void* const* d_in, const int* in_sizes, int n_in,
                              void* d_out, int out_size) {
    // Identify inputs by element count (robust to ordering):
    //   lfi    : B*V*H*W = 6,422,528
    //   f_maps : B*H*W*F = 8,388,608 (dead input — never touched)
    //   h_mask : B*F*H   = 65,536
    const float* lfi = nullptr;
    const float* h_mask = nullptr;
    for (int i = 0; i < n_in; i++) {
        if (in_sizes[i] == B_ * V_ * H_ * W_) lfi = (const float*)d_in[i];
        else if (in_sizes[i] == B_ * F_ * H_) h_mask = (const float*)d_in[i];
    }
    depth_cue_kernel<<<GRID, NTHREADS>>>(lfi, h_mask, (float2*)d_out);
}